// round 11
// baseline (speedup 1.0000x reference)
#include <cuda_runtime.h>

// RMSD quaternion loss: B=4096, N=2048.
// k1: one warp per half-batch. NEW: coalesced flat float4 loads (each LDG.128 spans
//     4 cache lines, not 12) staged through padded warp-private smem (4-phase
//     conflict-free STS/LDS), then the same 4-atom unpack + 10-sum accumulation.
// k2: FP32 Newton on the quartic char. poly of quaternion F (combines 2 halves).
// k3: final sum + sqrt. Plain launches (PDL removed: correlated with container failure).
// No atomics -> deterministic. Scratch in __device__ globals.

constexpr int BATCHES = 4096;
constexpr int NATOMS  = 2048;
constexpr int F4_PER_BATCH = NATOMS * 3 / 4;    // 1536 float4 per batch per tensor
constexpr int F4_PER_HALF  = F4_PER_BATCH / 2;  // 768
constexpr int K1_THREADS = 256;                 // 8 warps -> 8 warp-jobs per block
constexpr int K1_BLOCKS  = (BATCHES * 2) / 8;   // 1024
constexpr int K2_THREADS = 128;
constexpr int K2_BLOCKS  = BATCHES / K2_THREADS; // 32
constexpr int NJOBS = BATCHES * 2;              // 8192 (batch, half) warp-jobs
constexpr int MACROS = F4_PER_HALF / 96;        // 8 macro-iters (96 f4 = 128 atoms each)

// per-warp partials: SoA [10][NJOBS]
__device__ float  g_w[10 * NJOBS];
__device__ double g_part[K2_BLOCKS];

__global__ __launch_bounds__(K1_THREADS)
void k1_reduce(const float4* __restrict__ yp, const float4* __restrict__ yy)
{
    const int warp = threadIdx.x >> 5;
    const int lane = threadIdx.x & 31;
    const int job  = blockIdx.x * 8 + warp;      // 0..8191
    const int b    = job >> 1;
    const int half = job & 1;

    const float4* __restrict__ yp_h = yp + (size_t)b * F4_PER_BATCH + half * F4_PER_HALF;
    const float4* __restrict__ yy_h = yy + (size_t)b * F4_PER_BATCH + half * F4_PER_HALF;

    // padded staging: f4 j stored at slot j + j/24  (max 95+3=98 -> 100 slots)
    __shared__ float4 stage[8][2][100];
    float4 (&sp)[100] = stage[warp][0];
    float4 (&sq)[100] = stage[warp][1];

    float acc[10];
#pragma unroll
    for (int i = 0; i < 10; ++i) acc[i] = 0.0f;

    // write slots for this lane's three coalesced loads (j = lane, lane+32, lane+64)
    const int w0 = lane      + (lane      / 24);
    const int w1 = lane + 32 + ((lane + 32) / 24);
    const int w2 = lane + 64 + ((lane + 64) / 24);
    // read slots: lane reads f4s j = 3*lane + {0,1,2} -> slot 3*lane + (lane>>3) + r
    const int r0 = 3 * lane + (lane >> 3);

#pragma unroll 1
    for (int m = 0; m < MACROS; ++m) {
        const int base = m * 96;

        // coalesced loads: each LDG.128 covers 512B contiguous (4 lines)
        const float4 p0 = yp_h[base + lane];
        const float4 p1 = yp_h[base + lane + 32];
        const float4 p2 = yp_h[base + lane + 64];
        const float4 q0 = yy_h[base + lane];
        const float4 q1 = yy_h[base + lane + 32];
        const float4 q2 = yy_h[base + lane + 64];

        __syncwarp();          // previous iteration's reads are done
        sp[w0] = p0; sp[w1] = p1; sp[w2] = p2;
        sq[w0] = q0; sq[w1] = q1; sq[w2] = q2;
        __syncwarp();

        // lane's 4 atoms (48B contiguous) via conflict-free LDS.128
        const float4 a0 = sp[r0 + 0];
        const float4 a1 = sp[r0 + 1];
        const float4 a2 = sp[r0 + 2];
        const float4 b0 = sq[r0 + 0];
        const float4 b1 = sq[r0 + 1];
        const float4 b2 = sq[r0 + 2];

        const float px[4] = { a0.x, a0.w, a1.z, a2.y };
        const float py[4] = { a0.y, a1.x, a1.w, a2.z };
        const float pz[4] = { a0.z, a1.y, a2.x, a2.w };
        const float qx[4] = { b0.x, b0.w, b1.z, b2.y };
        const float qy[4] = { b0.y, b1.x, b1.w, b2.z };
        const float qz[4] = { b0.z, b1.y, b2.x, b2.w };

#pragma unroll
        for (int i = 0; i < 4; ++i) {
            acc[0] = fmaf(px[i], qx[i], acc[0]);
            acc[1] = fmaf(px[i], qy[i], acc[1]);
            acc[2] = fmaf(px[i], qz[i], acc[2]);
            acc[3] = fmaf(py[i], qx[i], acc[3]);
            acc[4] = fmaf(py[i], qy[i], acc[4]);
            acc[5] = fmaf(py[i], qz[i], acc[5]);
            acc[6] = fmaf(pz[i], qx[i], acc[6]);
            acc[7] = fmaf(pz[i], qy[i], acc[7]);
            acc[8] = fmaf(pz[i], qz[i], acc[8]);
            acc[9] = fmaf(px[i], px[i], acc[9]);
            acc[9] = fmaf(py[i], py[i], acc[9]);
            acc[9] = fmaf(pz[i], pz[i], acc[9]);
            acc[9] = fmaf(qx[i], qx[i], acc[9]);
            acc[9] = fmaf(qy[i], qy[i], acc[9]);
            acc[9] = fmaf(qz[i], qz[i], acc[9]);
        }
    }

    // warp-only reduction (no block sync)
#pragma unroll
    for (int i = 0; i < 10; ++i)
#pragma unroll
        for (int off = 16; off > 0; off >>= 1)
            acc[i] += __shfl_down_sync(0xffffffffu, acc[i], off);

    if (lane == 0) {
#pragma unroll
        for (int i = 0; i < 10; ++i)
            g_w[i * NJOBS + job] = acc[i];
    }
}

__device__ __forceinline__ float det3f(float a, float b, float c,
                                       float d, float e, float f,
                                       float g, float h, float i)
{
    return a * (e * i - f * h) - b * (d * i - f * g) + c * (d * h - e * g);
}

__global__ __launch_bounds__(K2_THREADS)
void k2_eigen()
{
    const int b = blockIdx.x * K2_THREADS + threadIdx.x;

    // combine the two half-batch partials
    float v[10];
#pragma unroll
    for (int i = 0; i < 10; ++i)
        v[i] = g_w[i * NJOBS + 2 * b] + g_w[i * NJOBS + 2 * b + 1];

    const float r00 = v[0], r01 = v[1], r02 = v[2];
    const float r10 = v[3], r11 = v[4], r12 = v[5];
    const float r20 = v[6], r21 = v[7], r22 = v[8];
    const float sqn = v[9];

    const float S = r00*r00 + r01*r01 + r02*r02
                  + r10*r10 + r11*r11 + r12*r12
                  + r20*r20 + r21*r21 + r22*r22;
    const float c2 = -2.0f * S;
    const float detR = r00 * (r11 * r22 - r12 * r21)
                     - r01 * (r10 * r22 - r12 * r20)
                     + r02 * (r10 * r21 - r11 * r20);
    const float c1 = -8.0f * detR;

    const float F00 =  r00 + r11 + r22;
    const float F01 =  r12 - r21;
    const float F02 =  r20 - r02;
    const float F03 =  r01 - r10;
    const float F11 =  r00 - r11 - r22;
    const float F12 =  r01 + r10;
    const float F13 =  r02 + r20;
    const float F22 = -r00 + r11 - r22;
    const float F23 =  r12 + r21;
    const float F33 = -r00 - r11 + r22;

    const float M00 = det3f(F11, F12, F13,  F12, F22, F23,  F13, F23, F33);
    const float M01 = det3f(F01, F12, F13,  F02, F22, F23,  F03, F23, F33);
    const float M02 = det3f(F01, F11, F13,  F02, F12, F23,  F03, F13, F33);
    const float M03 = det3f(F01, F11, F12,  F02, F12, F22,  F03, F13, F23);
    const float c0 = F00 * M00 - F01 * M01 + F02 * M02 - F03 * M03;

    // FP32 Newton from upper bound 2*sqrt(S) >= lmax (P' > 0 on [lmax, inf)).
    float lam = 2.0f * sqrtf(S);
#pragma unroll 1
    for (int it = 0; it < 16; ++it) {
        const float l2 = lam * lam;
        const float p  = ((l2 + c2) * lam + c1) * lam + c0;
        float dp = (4.0f * l2 + 2.0f * c2) * lam + c1;
        dp = fmaxf(dp, 1e-6f);
        lam -= __fdividef(p, dp);
    }

    double sd = (double)sqn - 2.0 * (double)lam;

    __shared__ double sdata[K2_THREADS];
    sdata[threadIdx.x] = sd;
    __syncthreads();
#pragma unroll
    for (int st = K2_THREADS / 2; st > 0; st >>= 1) {
        if (threadIdx.x < st) sdata[threadIdx.x] += sdata[threadIdx.x + st];
        __syncthreads();
    }
    if (threadIdx.x == 0) g_part[blockIdx.x] = sdata[0];
}

__global__ void k3_final(float* __restrict__ out)
{
    double v = (threadIdx.x < K2_BLOCKS) ? g_part[threadIdx.x] : 0.0;
#pragma unroll
    for (int off = 16; off > 0; off >>= 1)
        v += __shfl_down_sync(0xffffffffu, v, off);
    if (threadIdx.x == 0)
        out[0] = (float)sqrt(v / (double)NATOMS);
}

extern "C" void kernel_launch(void* const* d_in, const int* in_sizes, int n_in,
                              void* d_out, int out_size)
{
    const float4* yp = (const float4*)d_in[0]; // y_prime (B, N, 3)
    const float4* yy = (const float4*)d_in[1]; // y       (B, N, 3)
    float* out = (float*)d_out;

    k1_reduce<<<K1_BLOCKS, K1_THREADS>>>(yp, yy);
    k2_eigen<<<K2_BLOCKS, K2_THREADS>>>();
    k3_final<<<1, 32>>>(out);
}

// round 13
// speedup vs baseline: 1.1047x; 1.1047x over previous
#include <cuda_runtime.h>
#include <cstdint>

// RMSD quaternion loss: B=4096, N=2048.
// k1: block-per-batch. cp.async (LDGSTS.128) stages fully-coalesced flat float4
//     loads into padded smem (zero staging registers, L1 bypass, 4-line dedup per
//     warp access), then conflict-free LDS.128 of 3 consecutive f4 (4 atoms) per
//     thread -> 10-sum accumulation. Single 25.6KB buffer -> 8 blocks/SM.
// k2: FP32 Newton on the quartic char. poly of the quaternion F matrix.
// k3: final sum + sqrt. No atomics -> deterministic. Scratch in __device__ globals.

constexpr int BATCHES = 4096;
constexpr int NATOMS  = 2048;
constexpr int F4_PER_BATCH = NATOMS * 3 / 4;    // 1536 float4 per batch per tensor
constexpr int TILE_F4 = 768;                    // per tensor per tile (= 1024 atoms)
constexpr int NTILES  = F4_PER_BATCH / TILE_F4; // 2
constexpr int K1_THREADS = 256;
constexpr int K2_THREADS = 128;
constexpr int K2_BLOCKS  = BATCHES / K2_THREADS; // 32
constexpr int SLOTS = TILE_F4 + TILE_F4 / 24;   // 800 padded slots

// scratch: SoA [10][BATCHES]: r00 r01 r02 r10 r11 r12 r20 r21 r22 sqn
__device__ float  g_scr[10 * BATCHES];
__device__ double g_part[K2_BLOCKS];

__device__ __forceinline__ void cp_async16(unsigned int smem_addr, const float4* gptr)
{
    asm volatile("cp.async.cg.shared.global [%0], [%1], 16;\n"
                 :: "r"(smem_addr), "l"(gptr));
}
__device__ __forceinline__ void cp_async_commit() {
    asm volatile("cp.async.commit_group;\n");
}
__device__ __forceinline__ void cp_async_wait_all() {
    asm volatile("cp.async.wait_group 0;\n");
}

__global__ __launch_bounds__(K1_THREADS)
void k1_reduce(const float4* __restrict__ yp, const float4* __restrict__ yy)
{
    const int b = blockIdx.x;
    const int t = threadIdx.x;
    const float4* __restrict__ yp_b = yp + (size_t)b * F4_PER_BATCH;
    const float4* __restrict__ yy_b = yy + (size_t)b * F4_PER_BATCH;

    __shared__ float4 sp[SLOTS];
    __shared__ float4 sq[SLOTS];
    const unsigned int sp_base = (unsigned int)__cvta_generic_to_shared(sp);
    const unsigned int sq_base = (unsigned int)__cvta_generic_to_shared(sq);

    // issue slots for flat f4 j = t, t+256, t+512  (slot = j + j/24)
    const int j0 = t,       s0 = j0 + j0 / 24;
    const int j1 = t + 256, s1 = j1 + j1 / 24;
    const int j2 = t + 512, s2 = j2 + j2 / 24;
    // read base slot: f4s 3t,3t+1,3t+2 -> slots 3t + (t>>3) + {0,1,2}
    const int r0 = 3 * t + (t >> 3);

    float acc[10];
#pragma unroll
    for (int i = 0; i < 10; ++i) acc[i] = 0.0f;

#pragma unroll 1
    for (int tile = 0; tile < NTILES; ++tile) {
        const float4* gp = yp_b + tile * TILE_F4;
        const float4* gq = yy_b + tile * TILE_F4;

        __syncthreads();   // prior tile's smem reads complete before overwrite
        cp_async16(sp_base + s0 * 16, gp + j0);
        cp_async16(sp_base + s1 * 16, gp + j1);
        cp_async16(sp_base + s2 * 16, gp + j2);
        cp_async16(sq_base + s0 * 16, gq + j0);
        cp_async16(sq_base + s1 * 16, gq + j1);
        cp_async16(sq_base + s2 * 16, gq + j2);
        cp_async_commit();
        cp_async_wait_all();
        __syncthreads();   // all threads' async fills visible

        const float4 a0 = sp[r0 + 0];
        const float4 a1 = sp[r0 + 1];
        const float4 a2 = sp[r0 + 2];
        const float4 b0 = sq[r0 + 0];
        const float4 b1 = sq[r0 + 1];
        const float4 b2 = sq[r0 + 2];

        const float px[4] = { a0.x, a0.w, a1.z, a2.y };
        const float py[4] = { a0.y, a1.x, a1.w, a2.z };
        const float pz[4] = { a0.z, a1.y, a2.x, a2.w };
        const float qx[4] = { b0.x, b0.w, b1.z, b2.y };
        const float qy[4] = { b0.y, b1.x, b1.w, b2.z };
        const float qz[4] = { b0.z, b1.y, b2.x, b2.w };

#pragma unroll
        for (int i = 0; i < 4; ++i) {
            acc[0] = fmaf(px[i], qx[i], acc[0]);
            acc[1] = fmaf(px[i], qy[i], acc[1]);
            acc[2] = fmaf(px[i], qz[i], acc[2]);
            acc[3] = fmaf(py[i], qx[i], acc[3]);
            acc[4] = fmaf(py[i], qy[i], acc[4]);
            acc[5] = fmaf(py[i], qz[i], acc[5]);
            acc[6] = fmaf(pz[i], qx[i], acc[6]);
            acc[7] = fmaf(pz[i], qy[i], acc[7]);
            acc[8] = fmaf(pz[i], qz[i], acc[8]);
            acc[9] = fmaf(px[i], px[i], acc[9]);
            acc[9] = fmaf(py[i], py[i], acc[9]);
            acc[9] = fmaf(pz[i], pz[i], acc[9]);
            acc[9] = fmaf(qx[i], qx[i], acc[9]);
            acc[9] = fmaf(qy[i], qy[i], acc[9]);
            acc[9] = fmaf(qz[i], qz[i], acc[9]);
        }
    }

    // block reduce (warp shuffles + smem, deterministic)
#pragma unroll
    for (int i = 0; i < 10; ++i)
#pragma unroll
        for (int off = 16; off > 0; off >>= 1)
            acc[i] += __shfl_down_sync(0xffffffffu, acc[i], off);

    __shared__ float smr[K1_THREADS / 32][10];
    const int warp = t >> 5;
    const int lane = t & 31;
    if (lane == 0) {
#pragma unroll
        for (int i = 0; i < 10; ++i) smr[warp][i] = acc[i];
    }
    __syncthreads();

    if (warp == 0) {
        float v[10];
#pragma unroll
        for (int i = 0; i < 10; ++i)
            v[i] = (lane < (K1_THREADS / 32)) ? smr[lane][i] : 0.0f;
#pragma unroll
        for (int i = 0; i < 10; ++i)
#pragma unroll
            for (int off = (K1_THREADS / 64); off > 0; off >>= 1)
                v[i] += __shfl_down_sync(0xffffffffu, v[i], off);
        if (lane == 0) {
#pragma unroll
            for (int i = 0; i < 10; ++i)
                g_scr[i * BATCHES + b] = v[i];
        }
    }
}

__device__ __forceinline__ float det3f(float a, float b, float c,
                                       float d, float e, float f,
                                       float g, float h, float i)
{
    return a * (e * i - f * h) - b * (d * i - f * g) + c * (d * h - e * g);
}

__global__ __launch_bounds__(K2_THREADS)
void k2_eigen()
{
    const int b = blockIdx.x * K2_THREADS + threadIdx.x;

    const float r00 = g_scr[0 * BATCHES + b];
    const float r01 = g_scr[1 * BATCHES + b];
    const float r02 = g_scr[2 * BATCHES + b];
    const float r10 = g_scr[3 * BATCHES + b];
    const float r11 = g_scr[4 * BATCHES + b];
    const float r12 = g_scr[5 * BATCHES + b];
    const float r20 = g_scr[6 * BATCHES + b];
    const float r21 = g_scr[7 * BATCHES + b];
    const float r22 = g_scr[8 * BATCHES + b];
    const float sqn = g_scr[9 * BATCHES + b];

    const float S = r00*r00 + r01*r01 + r02*r02
                  + r10*r10 + r11*r11 + r12*r12
                  + r20*r20 + r21*r21 + r22*r22;
    const float c2 = -2.0f * S;
    const float detR = r00 * (r11 * r22 - r12 * r21)
                     - r01 * (r10 * r22 - r12 * r20)
                     + r02 * (r10 * r21 - r11 * r20);
    const float c1 = -8.0f * detR;

    // Quaternion key matrix F (symmetric, trace 0)
    const float F00 =  r00 + r11 + r22;
    const float F01 =  r12 - r21;
    const float F02 =  r20 - r02;
    const float F03 =  r01 - r10;
    const float F11 =  r00 - r11 - r22;
    const float F12 =  r01 + r10;
    const float F13 =  r02 + r20;
    const float F22 = -r00 + r11 - r22;
    const float F23 =  r12 + r21;
    const float F33 = -r00 - r11 + r22;

    const float M00 = det3f(F11, F12, F13,  F12, F22, F23,  F13, F23, F33);
    const float M01 = det3f(F01, F12, F13,  F02, F22, F23,  F03, F23, F33);
    const float M02 = det3f(F01, F11, F13,  F02, F12, F23,  F03, F13, F33);
    const float M03 = det3f(F01, F11, F12,  F02, F12, F22,  F03, F13, F23);
    const float c0 = F00 * M00 - F01 * M01 + F02 * M02 - F03 * M03;

    // FP32 Newton from upper bound 2*sqrt(S) >= lmax (P' > 0 on [lmax, inf)).
    float lam = 2.0f * sqrtf(S);
#pragma unroll 1
    for (int it = 0; it < 16; ++it) {
        const float l2 = lam * lam;
        const float p  = ((l2 + c2) * lam + c1) * lam + c0;
        float dp = (4.0f * l2 + 2.0f * c2) * lam + c1;
        dp = fmaxf(dp, 1e-6f);
        lam -= __fdividef(p, dp);
    }

    double sd = (double)sqn - 2.0 * (double)lam;

    // deterministic block tree reduce
    __shared__ double sdata[K2_THREADS];
    sdata[threadIdx.x] = sd;
    __syncthreads();
#pragma unroll
    for (int st = K2_THREADS / 2; st > 0; st >>= 1) {
        if (threadIdx.x < st) sdata[threadIdx.x] += sdata[threadIdx.x + st];
        __syncthreads();
    }
    if (threadIdx.x == 0) g_part[blockIdx.x] = sdata[0];
}

__global__ void k3_final(float* __restrict__ out)
{
    double v = (threadIdx.x < K2_BLOCKS) ? g_part[threadIdx.x] : 0.0;
#pragma unroll
    for (int off = 16; off > 0; off >>= 1)
        v += __shfl_down_sync(0xffffffffu, v, off);
    if (threadIdx.x == 0)
        out[0] = (float)sqrt(v / (double)NATOMS);
}

extern "C" void kernel_launch(void* const* d_in, const int* in_sizes, int n_in,
                              void* d_out, int out_size)
{
    const float4* yp = (const float4*)d_in[0]; // y_prime (B, N, 3)
    const float4* yy = (const float4*)d_in[1]; // y       (B, N, 3)
    float* out = (float*)d_out;

    k1_reduce<<<BATCHES, K1_THREADS>>>(yp, yy);
    k2_eigen<<<K2_BLOCKS, K2_THREADS>>>();
    k3_final<<<1, 32>>>(out);
}